// round 2
// baseline (speedup 1.0000x reference)
#include <cuda_runtime.h>

// BaseGraphPooling: segment-mean over sorted node_batch.
// node_h: [N, 128] fp32, node_batch: [N] int32 (JAX x64-disabled!), out: [G, 128] fp32.
// One CTA per graph g: binary-search segment bounds, stream-sum rows, divide by count.

__device__ __forceinline__ int lower_bound_i32(const int* __restrict__ a,
                                               int n, int key) {
    int lo = 0, hi = n;
    while (lo < hi) {
        int mid = (lo + hi) >> 1;
        if (a[mid] < key) lo = mid + 1; else hi = mid;
    }
    return lo;
}

__device__ __forceinline__ float4 f4add(float4 a, float4 b) {
    a.x += b.x; a.y += b.y; a.z += b.z; a.w += b.w; return a;
}

__global__ __launch_bounds__(256, 8)
void segment_mean_kernel(const float4* __restrict__ h,    // N*32 float4
                         const int* __restrict__ batch,   // N (int32)
                         float4* __restrict__ out,        // G*32 float4
                         int N) {
    const int g   = blockIdx.x;
    const int tid = threadIdx.x;
    const int c   = tid & 31;   // float4 column within row (0..31)
    const int r   = tid >> 5;   // row phase (0..7)

    // Uniform binary search (all threads same path; L1/L2-resident after first CTAs)
    const int start = lower_bound_i32(batch, N, g);
    const int end   = lower_bound_i32(batch, N, g + 1);
    const int count = end - start;

    float4 a0 = make_float4(0.f, 0.f, 0.f, 0.f);
    float4 a1 = a0, a2 = a0, a3 = a0;

    // Main loop: 8 rows per phase, 4x unrolled => 4 independent LDG.128 in flight/thread
    int i = start + r;
    for (; i + 24 < end; i += 32) {
        float4 v0 = h[(size_t)(i     ) * 32 + c];
        float4 v1 = h[(size_t)(i +  8) * 32 + c];
        float4 v2 = h[(size_t)(i + 16) * 32 + c];
        float4 v3 = h[(size_t)(i + 24) * 32 + c];
        a0 = f4add(a0, v0);
        a1 = f4add(a1, v1);
        a2 = f4add(a2, v2);
        a3 = f4add(a3, v3);
    }
    for (; i < end; i += 8)
        a0 = f4add(a0, h[(size_t)i * 32 + c]);

    float4 acc = f4add(f4add(a0, a1), f4add(a2, a3));

    // Cross-row-phase reduction via shared memory
    __shared__ float4 smem[256];
    smem[tid] = acc;
    __syncthreads();

    if (r == 0) {
        float4 s = smem[c];
        #pragma unroll
        for (int p = 1; p < 8; p++)
            s = f4add(s, smem[p * 32 + c]);
        float inv = 1.0f / (float)max(count, 1);
        s.x *= inv; s.y *= inv; s.z *= inv; s.w *= inv;
        out[(size_t)g * 32 + c] = s;
    }
}

extern "C" void kernel_launch(void* const* d_in, const int* in_sizes, int n_in,
                              void* d_out, int out_size) {
    const float4* h      = (const float4*)d_in[0];
    const int*    batch  = (const int*)d_in[1];
    const int N = in_sizes[1];          // number of nodes
    const int G = out_size / 128;       // number of graphs

    segment_mean_kernel<<<G, 256>>>(h, batch, (float4*)d_out, N);
}

// round 3
// speedup vs baseline: 1.0380x; 1.0380x over previous
#include <cuda_runtime.h>

// BaseGraphPooling: segment-mean over sorted node_batch.
// node_h: [N,128] fp32, node_batch: [N] int32 sorted, out: [G,128] fp32.
//
// Plan: 3 graph-captured launches.
//  1) zero_out: zero d_out (poisoned by harness; atomics accumulate into it)
//  2) chunk_sum: 1184 CTAs (= 148 SMs x occ 8), each owns a fixed contiguous
//     row chunk -> perfect per-SM byte balance. Sorted indices => chunk spans
//     ~1-2 segments; flush partial sums with red.global.add.v4.f32.
//  3) divide: per-graph count via binary search, scale by 1/max(count,1).

#define NUM_CTAS 1184   // 148 SMs * 8 CTAs/SM, exactly one wave

__device__ __forceinline__ int lower_bound_i32(const int* __restrict__ a,
                                               int n, int key) {
    int lo = 0, hi = n;
    while (lo < hi) {
        int mid = (lo + hi) >> 1;
        if (a[mid] < key) lo = mid + 1; else hi = mid;
    }
    return lo;
}

__device__ __forceinline__ float4 f4add(float4 a, float4 b) {
    a.x += b.x; a.y += b.y; a.z += b.z; a.w += b.w; return a;
}

__device__ __forceinline__ void red_add_v4(float4* addr, float4 v) {
    asm volatile("red.global.add.v4.f32 [%0], {%1, %2, %3, %4};"
                 :: "l"(addr), "f"(v.x), "f"(v.y), "f"(v.z), "f"(v.w)
                 : "memory");
}

__global__ void zero_out_kernel(float4* __restrict__ out, int n4) {
    int i = blockIdx.x * blockDim.x + threadIdx.x;
    if (i < n4) out[i] = make_float4(0.f, 0.f, 0.f, 0.f);
}

__global__ __launch_bounds__(256, 8)
void chunk_sum_kernel(const float4* __restrict__ h,    // N*32 float4
                      const int* __restrict__ batch,   // N int32, sorted
                      float4* __restrict__ out,        // G*32 float4
                      int N, int rows_per_cta) {
    const int tid = threadIdx.x;
    const int c   = tid & 31;   // float4 column (0..31)
    const int r   = tid >> 5;   // row phase (0..7)

    int c0 = blockIdx.x * rows_per_cta;
    int c1 = min(c0 + rows_per_cta, N);
    if (c0 >= c1) return;

    __shared__ float4 smem[256];

    int s = c0;
    while (s < c1) {
        const int g = batch[s];                 // uniform: current segment id
        // upper_bound(g) within [s, c1) -> end of this sub-segment
        int lo = s, hi = c1;
        while (lo < hi) {
            int mid = (lo + hi) >> 1;
            if (batch[mid] <= g) lo = mid + 1; else hi = mid;
        }
        const int e = lo;

        float4 a0 = make_float4(0.f, 0.f, 0.f, 0.f);
        float4 a1 = a0, a2 = a0, a3 = a0;

        int i = s + r;
        for (; i + 24 < e; i += 32) {
            float4 v0 = __ldcs(&h[(size_t)(i     ) * 32 + c]);
            float4 v1 = __ldcs(&h[(size_t)(i +  8) * 32 + c]);
            float4 v2 = __ldcs(&h[(size_t)(i + 16) * 32 + c]);
            float4 v3 = __ldcs(&h[(size_t)(i + 24) * 32 + c]);
            a0 = f4add(a0, v0);
            a1 = f4add(a1, v1);
            a2 = f4add(a2, v2);
            a3 = f4add(a3, v3);
        }
        for (; i < e; i += 8)
            a0 = f4add(a0, __ldcs(&h[(size_t)i * 32 + c]));

        smem[tid] = f4add(f4add(a0, a1), f4add(a2, a3));
        __syncthreads();

        if (r == 0) {
            float4 acc = smem[c];
            #pragma unroll
            for (int p = 1; p < 8; p++)
                acc = f4add(acc, smem[p * 32 + c]);
            red_add_v4(&out[(size_t)g * 32 + c], acc);
        }
        __syncthreads();   // smem reuse safety for next sub-segment

        s = e;
    }
}

__global__ void divide_kernel(const int* __restrict__ batch,
                              float4* __restrict__ out,
                              int N) {
    const int g = blockIdx.x;
    const int c = threadIdx.x;   // 0..31
    const int start = lower_bound_i32(batch, N, g);
    const int end   = lower_bound_i32(batch, N, g + 1);
    const float inv = 1.0f / (float)max(end - start, 1);
    float4 v = out[(size_t)g * 32 + c];
    v.x *= inv; v.y *= inv; v.z *= inv; v.w *= inv;
    out[(size_t)g * 32 + c] = v;
}

extern "C" void kernel_launch(void* const* d_in, const int* in_sizes, int n_in,
                              void* d_out, int out_size) {
    const float4* h     = (const float4*)d_in[0];
    const int*    batch = (const int*)d_in[1];
    const int N = in_sizes[1];       // number of nodes
    const int G = out_size / 128;    // number of graphs
    const int n4 = out_size / 4;     // float4 count of output

    zero_out_kernel<<<(n4 + 255) / 256, 256>>>((float4*)d_out, n4);

    int rows_per_cta = (N + NUM_CTAS - 1) / NUM_CTAS;
    chunk_sum_kernel<<<NUM_CTAS, 256>>>(h, batch, (float4*)d_out, N, rows_per_cta);

    divide_kernel<<<G, 32>>>(batch, (float4*)d_out, N);
}

// round 4
// speedup vs baseline: 1.0532x; 1.0147x over previous
#include <cuda_runtime.h>

// BaseGraphPooling: segment-mean over sorted node_batch.
// node_h: [N,128] fp32, node_batch: [N] int32 sorted, out: [G,128] fp32.
//
// 3 launches chained with Programmatic Dependent Launch so the tiny
// zero/divide kernels overlap the big streaming kernel:
//  1) zero_out  : zero d_out (poisoned by harness)
//  2) chunk_sum : 1184 CTAs (148 SMs x 8), fixed contiguous row chunks ->
//                 perfect per-SM byte balance; sorted indices => 1-2 segments
//                 per chunk; partial sums flushed via red.global.add.v4.f32.
//                 PDL: starts under zero_out, griddepsync before first red.
//  3) divide    : per-graph count via binary search, scale by 1/max(count,1).
//                 PDL: binary searches overlap chunk_sum's drain tail.

#define NUM_CTAS 1184   // 148 SMs * 8 CTAs/SM, exactly one wave

__device__ __forceinline__ int lower_bound_i32(const int* __restrict__ a,
                                               int n, int key) {
    int lo = 0, hi = n;
    while (lo < hi) {
        int mid = (lo + hi) >> 1;
        if (a[mid] < key) lo = mid + 1; else hi = mid;
    }
    return lo;
}

__device__ __forceinline__ float4 f4add(float4 a, float4 b) {
    a.x += b.x; a.y += b.y; a.z += b.z; a.w += b.w; return a;
}

__device__ __forceinline__ void red_add_v4(float4* addr, float4 v) {
    asm volatile("red.global.add.v4.f32 [%0], {%1, %2, %3, %4};"
                 :: "l"(addr), "f"(v.x), "f"(v.y), "f"(v.z), "f"(v.w)
                 : "memory");
}

__global__ void zero_out_kernel(float4* __restrict__ out, int n4) {
    int i = blockIdx.x * blockDim.x + threadIdx.x;
    if (i < n4) out[i] = make_float4(0.f, 0.f, 0.f, 0.f);
}

__global__ __launch_bounds__(256, 8)
void chunk_sum_kernel(const float4* __restrict__ h,    // N*32 float4
                      const int* __restrict__ batch,   // N int32, sorted
                      float4* __restrict__ out,        // G*32 float4
                      int N, int rows_per_cta) {
    const int tid = threadIdx.x;
    const int c   = tid & 31;   // float4 column (0..31)
    const int r   = tid >> 5;   // row phase (0..7)

    int c0 = blockIdx.x * rows_per_cta;
    int c1 = min(c0 + rows_per_cta, N);
    if (c0 >= c1) {
        cudaGridDependencySynchronize();
        return;
    }

    __shared__ float4 smem[256];
    bool synced = false;

    int s = c0;
    while (s < c1) {
        const int g = batch[s];                 // uniform: current segment id
        // upper_bound(g) within [s, c1) -> end of this sub-segment
        int lo = s, hi = c1;
        while (lo < hi) {
            int mid = (lo + hi) >> 1;
            if (batch[mid] <= g) lo = mid + 1; else hi = mid;
        }
        const int e = lo;

        float4 a0 = make_float4(0.f, 0.f, 0.f, 0.f);
        float4 a1 = a0, a2 = a0, a3 = a0;

        int i = s + r;
        for (; i + 24 < e; i += 32) {
            float4 v0 = __ldcs(&h[(size_t)(i     ) * 32 + c]);
            float4 v1 = __ldcs(&h[(size_t)(i +  8) * 32 + c]);
            float4 v2 = __ldcs(&h[(size_t)(i + 16) * 32 + c]);
            float4 v3 = __ldcs(&h[(size_t)(i + 24) * 32 + c]);
            a0 = f4add(a0, v0);
            a1 = f4add(a1, v1);
            a2 = f4add(a2, v2);
            a3 = f4add(a3, v3);
        }
        for (; i < e; i += 8)
            a0 = f4add(a0, __ldcs(&h[(size_t)i * 32 + c]));

        smem[tid] = f4add(f4add(a0, a1), f4add(a2, a3));
        __syncthreads();

        // d_out must be zeroed before the first atomic flush; everything
        // above (h/batch loads, accumulation) is independent of zero_out.
        if (!synced) {
            cudaGridDependencySynchronize();
            synced = true;
        }

        if (r == 0) {
            float4 acc = smem[c];
            #pragma unroll
            for (int p = 1; p < 8; p++)
                acc = f4add(acc, smem[p * 32 + c]);
            red_add_v4(&out[(size_t)g * 32 + c], acc);
        }
        __syncthreads();   // smem reuse safety for next sub-segment

        s = e;
    }
}

__global__ void divide_kernel(const int* __restrict__ batch,
                              float4* __restrict__ out,
                              int N) {
    const int g = blockIdx.x;
    const int c = threadIdx.x;   // 0..31
    // Binary searches depend only on batch -> overlap chunk_sum's tail.
    const int start = lower_bound_i32(batch, N, g);
    const int end   = lower_bound_i32(batch, N, g + 1);
    const float inv = 1.0f / (float)max(end - start, 1);

    cudaGridDependencySynchronize();   // wait for all chunk_sum atomics

    float4 v = out[(size_t)g * 32 + c];
    v.x *= inv; v.y *= inv; v.z *= inv; v.w *= inv;
    out[(size_t)g * 32 + c] = v;
}

extern "C" void kernel_launch(void* const* d_in, const int* in_sizes, int n_in,
                              void* d_out, int out_size) {
    const float4* h     = (const float4*)d_in[0];
    const int*    batch = (const int*)d_in[1];
    const int N = in_sizes[1];       // number of nodes
    const int G = out_size / 128;    // number of graphs
    const int n4 = out_size / 4;     // float4 count of output

    zero_out_kernel<<<(n4 + 255) / 256, 256>>>((float4*)d_out, n4);

    cudaLaunchAttribute pdl[1];
    pdl[0].id = cudaLaunchAttributeProgrammaticStreamSerialization;
    pdl[0].val.programmaticStreamSerializationAllowed = 1;

    int rows_per_cta = (N + NUM_CTAS - 1) / NUM_CTAS;
    {
        cudaLaunchConfig_t cfg = {};
        cfg.gridDim  = dim3(NUM_CTAS, 1, 1);
        cfg.blockDim = dim3(256, 1, 1);
        cfg.stream   = 0;
        cfg.attrs    = pdl;
        cfg.numAttrs = 1;
        cudaLaunchKernelEx(&cfg, chunk_sum_kernel,
                           h, batch, (float4*)d_out, N, rows_per_cta);
    }
    {
        cudaLaunchConfig_t cfg = {};
        cfg.gridDim  = dim3(G, 1, 1);
        cfg.blockDim = dim3(32, 1, 1);
        cfg.stream   = 0;
        cfg.attrs    = pdl;
        cfg.numAttrs = 1;
        cudaLaunchKernelEx(&cfg, divide_kernel, batch, (float4*)d_out, N);
    }
}